// round 1
// baseline (speedup 1.0000x reference)
#include <cuda_runtime.h>

#define NV   120000
#define ND   30000
#define NV2  60000
#define NPTS 400000
#define CD   128
#define HD   64

// ---------------- scratch (static device globals; no allocation) ----------------
__device__ float g_ds[ND * CD];        // segment sums of x
__device__ float g_cntd[ND];
__device__ float g_identity[NV * CD];
__device__ float g_t1[ND * HD];
__device__ float g_t2[ND * HD];
__device__ float g_hm[ND * CD];
__device__ float g_pfea[NV2 * CD];     // segment sums of pts
__device__ float g_cntv2[NV2];
__device__ float g_stats[512];         // [0:64) sum1 [128:192) sq1 [256:320) sum2 [384:448) sq2

__device__ __forceinline__ float lrelu(float x) { return x > 0.f ? x : 0.1f * x; }

__device__ __forceinline__ void red_add_v4(float* p, float4 v) {
    asm volatile("red.global.add.v4.f32 [%0], {%1,%2,%3,%4};"
                 :: "l"(p), "f"(v.x), "f"(v.y), "f"(v.z), "f"(v.w) : "memory");
}

// ---------------- zero scratch ----------------
__global__ void k_zero() {
    int idx = blockIdx.x * blockDim.x + threadIdx.x;
    int stride = gridDim.x * blockDim.x;
    for (int i = idx; i < ND * CD; i += stride)  g_ds[i] = 0.f;
    for (int i = idx; i < ND; i += stride)       g_cntd[i] = 0.f;
    for (int i = idx; i < NV2 * CD; i += stride) g_pfea[i] = 0.f;
    for (int i = idx; i < NV2; i += stride)      g_cntv2[i] = 0.f;
    for (int i = idx; i < 512; i += stride)      g_stats[i] = 0.f;
}

// ---------------- segment counts ----------------
__global__ void k_counts(const int* __restrict__ inv, const int* __restrict__ cin) {
    int i = blockIdx.x * blockDim.x + threadIdx.x;
    if (i < NV)   atomicAdd(&g_cntd[inv[i]], 1.0f);
    if (i < NPTS) atomicAdd(&g_cntv2[cin[i]], 1.0f);
}

// ---------------- shared GEMM microkernel: 128x128 tile, BK=8, 8x8/thread ----------------
__device__ __forceinline__ void gemm8(const float (* __restrict__ As)[128],
                                      const float (* __restrict__ Bs)[128],
                                      int tx, int ty, float acc[8][8]) {
#pragma unroll
    for (int k = 0; k < 8; ++k) {
        float4 a0 = *(const float4*)&As[k][ty * 8];
        float4 a1 = *(const float4*)&As[k][ty * 8 + 4];
        float4 b0 = *(const float4*)&Bs[k][tx * 8];
        float4 b1 = *(const float4*)&Bs[k][tx * 8 + 4];
        float av[8] = {a0.x, a0.y, a0.z, a0.w, a1.x, a1.y, a1.z, a1.w};
        float bv[8] = {b0.x, b0.y, b0.z, b0.w, b1.x, b1.y, b1.z, b1.w};
#pragma unroll
        for (int i = 0; i < 8; ++i)
#pragma unroll
            for (int j = 0; j < 8; ++j)
                acc[i][j] += av[i] * bv[j];
    }
}

// ---------------- identity = lrelu((f+v) @ W_in + b_in); fused scatter-add of x to g_ds ----------------
__global__ void __launch_bounds__(256) k_identity(
    const float* __restrict__ feat, const float* __restrict__ vfea,
    const int* __restrict__ inv,
    const float* __restrict__ W, const float* __restrict__ bias) {
    __shared__ float As[2][8][128];
    __shared__ float Bs[2][8][128];
    const int tid = threadIdx.x;
    const int tx = tid & 15, ty = tid >> 4;
    const int m0 = blockIdx.x * 128;
    const int arow = tid >> 1;
    const int acol = (tid & 1) * 4;
    const int grow = m0 + arow;
    const bool rvalid = grow < NV;
    const int seg = rvalid ? inv[grow] : 0;
    const int brow = tid >> 5;
    const int bcol = (tid & 31) * 4;

    float acc[8][8];
#pragma unroll
    for (int i = 0; i < 8; ++i)
#pragma unroll
        for (int j = 0; j < 8; ++j) acc[i][j] = 0.f;

    float4 aReg = make_float4(0, 0, 0, 0), bReg;
    if (rvalid) {
        float4 f = *(const float4*)(feat + (size_t)grow * CD + acol);
        float4 v = *(const float4*)(vfea + (size_t)grow * CD + acol);
        aReg = make_float4(f.x + v.x, f.y + v.y, f.z + v.z, f.w + v.w);
        red_add_v4(g_ds + (size_t)seg * CD + acol, aReg);
    }
    bReg = *(const float4*)(W + brow * CD + bcol);
    As[0][acol + 0][arow] = aReg.x; As[0][acol + 1][arow] = aReg.y;
    As[0][acol + 2][arow] = aReg.z; As[0][acol + 3][arow] = aReg.w;
    *(float4*)&Bs[0][brow][bcol] = bReg;
    __syncthreads();

    const int NC = 16;  // K = 128
    for (int c = 0; c < NC; ++c) {
        const int cur = c & 1;
        if (c + 1 < NC) {
            int col = (c + 1) * 8 + acol;
            if (rvalid) {
                float4 f = *(const float4*)(feat + (size_t)grow * CD + col);
                float4 v = *(const float4*)(vfea + (size_t)grow * CD + col);
                aReg = make_float4(f.x + v.x, f.y + v.y, f.z + v.z, f.w + v.w);
                red_add_v4(g_ds + (size_t)seg * CD + col, aReg);
            } else aReg = make_float4(0, 0, 0, 0);
            bReg = *(const float4*)(W + ((c + 1) * 8 + brow) * CD + bcol);
        }
        gemm8(As[cur], Bs[cur], tx, ty, acc);
        if (c + 1 < NC) {
            const int nb = cur ^ 1;
            As[nb][acol + 0][arow] = aReg.x; As[nb][acol + 1][arow] = aReg.y;
            As[nb][acol + 2][arow] = aReg.z; As[nb][acol + 3][arow] = aReg.w;
            *(float4*)&Bs[nb][brow][bcol] = bReg;
        }
        __syncthreads();
    }

    float bb[8];
#pragma unroll
    for (int j = 0; j < 8; ++j) bb[j] = bias[tx * 8 + j];
#pragma unroll
    for (int i = 0; i < 8; ++i) {
        int r = m0 + ty * 8 + i;
        if (r < NV) {
            float o[8];
#pragma unroll
            for (int j = 0; j < 8; ++j) o[j] = lrelu(acc[i][j] + bb[j]);
            *(float4*)(g_identity + (size_t)r * CD + tx * 8)     = make_float4(o[0], o[1], o[2], o[3]);
            *(float4*)(g_identity + (size_t)r * CD + tx * 8 + 4) = make_float4(o[4], o[5], o[6], o[7]);
        }
    }
}

// ---------------- PPmodel stage 1: t1 = lrelu((ds_sum/cnt) @ W1 + b1), accumulate stats ----------------
__global__ void __launch_bounds__(64) k_mlp1(const float* __restrict__ W, const float* __restrict__ bias) {
    __shared__ float row[128];
    const int tid = threadIdx.x;
    const float bj = bias[tid];
    float ls = 0.f, lsq = 0.f;
    for (int r = blockIdx.x; r < ND; r += gridDim.x) {
        float ic = 1.0f / fmaxf(g_cntd[r], 1.0f);
        for (int c = tid; c < 128; c += 64) row[c] = g_ds[(size_t)r * CD + c] * ic;
        __syncthreads();
        float a0 = 0, a1 = 0, a2 = 0, a3 = 0;
#pragma unroll 8
        for (int k = 0; k < 128; k += 4) {
            a0 += row[k + 0] * W[(k + 0) * 64 + tid];
            a1 += row[k + 1] * W[(k + 1) * 64 + tid];
            a2 += row[k + 2] * W[(k + 2) * 64 + tid];
            a3 += row[k + 3] * W[(k + 3) * 64 + tid];
        }
        float v = lrelu(a0 + a1 + a2 + a3 + bj);
        g_t1[(size_t)r * 64 + tid] = v;
        ls += v; lsq += v * v;
        __syncthreads();
    }
    atomicAdd(&g_stats[tid], ls);
    atomicAdd(&g_stats[128 + tid], lsq);
}

// ---------------- PPmodel stage 2: t2 = lrelu(BN1(t1) @ W2 + b2), accumulate stats ----------------
__global__ void __launch_bounds__(64) k_mlp2(const float* __restrict__ gam, const float* __restrict__ bet,
                                             const float* __restrict__ W, const float* __restrict__ bias) {
    __shared__ float row[64];
    __shared__ float amul[64], aadd[64];
    const int tid = threadIdx.x;
    {
        const float im = 1.0f / (float)ND;
        float m = g_stats[tid] * im;
        float v = g_stats[128 + tid] * im - m * m;
        float rs = rsqrtf(v + 1e-5f);
        float gm = rs * gam[tid];
        amul[tid] = gm; aadd[tid] = bet[tid] - m * gm;
    }
    __syncthreads();
    const float bj = bias[tid];
    float ls = 0.f, lsq = 0.f;
    for (int r = blockIdx.x; r < ND; r += gridDim.x) {
        row[tid] = g_t1[(size_t)r * 64 + tid] * amul[tid] + aadd[tid];
        __syncthreads();
        float a0 = 0, a1 = 0, a2 = 0, a3 = 0;
#pragma unroll 8
        for (int k = 0; k < 64; k += 4) {
            a0 += row[k + 0] * W[(k + 0) * 64 + tid];
            a1 += row[k + 1] * W[(k + 1) * 64 + tid];
            a2 += row[k + 2] * W[(k + 2) * 64 + tid];
            a3 += row[k + 3] * W[(k + 3) * 64 + tid];
        }
        float v = lrelu(a0 + a1 + a2 + a3 + bj);
        g_t2[(size_t)r * 64 + tid] = v;
        ls += v; lsq += v * v;
        __syncthreads();
    }
    atomicAdd(&g_stats[256 + tid], ls);
    atomicAdd(&g_stats[384 + tid], lsq);
}

// ---------------- PPmodel stage 3: hm = lrelu(BN2(t2) @ W3 + b3) ----------------
__global__ void __launch_bounds__(128) k_mlp3(const float* __restrict__ gam, const float* __restrict__ bet,
                                              const float* __restrict__ W, const float* __restrict__ bias) {
    __shared__ float row[64];
    __shared__ float amul[64], aadd[64];
    const int tid = threadIdx.x;
    if (tid < 64) {
        const float im = 1.0f / (float)ND;
        float m = g_stats[256 + tid] * im;
        float v = g_stats[384 + tid] * im - m * m;
        float rs = rsqrtf(v + 1e-5f);
        float gm = rs * gam[tid];
        amul[tid] = gm; aadd[tid] = bet[tid] - m * gm;
    }
    __syncthreads();
    const float bj = bias[tid];
    for (int r = blockIdx.x; r < ND; r += gridDim.x) {
        if (tid < 64) row[tid] = g_t2[(size_t)r * 64 + tid] * amul[tid] + aadd[tid];
        __syncthreads();
        float a0 = 0, a1 = 0, a2 = 0, a3 = 0;
#pragma unroll 8
        for (int k = 0; k < 64; k += 4) {
            a0 += row[k + 0] * W[(k + 0) * 128 + tid];
            a1 += row[k + 1] * W[(k + 1) * 128 + tid];
            a2 += row[k + 2] * W[(k + 2) * 128 + tid];
            a3 += row[k + 3] * W[(k + 3) * 128 + tid];
        }
        float v = lrelu(a0 + a1 + a2 + a3 + bj);
        g_hm[(size_t)r * CD + tid] = v;
        __syncthreads();
    }
}

// ---------------- fused point path:
//   A[p] = [identity[cil[p]] | hm[inv[cil[p]]]]  (gathered, K=256)
//   H = lrelu(A @ Wo1 + bo1)   (stays in SMEM)
//   Y = H @ Wo2 + bo2
//   red-add Y into g_pfea[cin[p]]
// ----------------
__global__ void __launch_bounds__(256, 2) k_points(
    const int* __restrict__ cil, const int* __restrict__ cin, const int* __restrict__ inv,
    const float* __restrict__ Wo1, const float* __restrict__ bo1,
    const float* __restrict__ Wo2, const float* __restrict__ bo2) {
    extern __shared__ float sm[];
    float (*As)[8][128] = (float (*)[8][128])(sm);           // 2048 floats
    float (*Bs)[8][128] = (float (*)[8][128])(sm + 2048);    // 2048 floats
    float (*Hs)[132]    = (float (*)[132])(sm + 4096);       // 128*132 = 16896 floats
    int* sv = (int*)(sm + 20992);
    int* sw = sv + 128;
    int* ss = sw + 128;

    const int tid = threadIdx.x;
    const int tx = tid & 15, ty = tid >> 4;
    const int m0 = blockIdx.x * 128;           // NPTS % 128 == 0, no guards
    const int arow = tid >> 1;
    const int acol = (tid & 1) * 4;
    const int brow = tid >> 5;
    const int bcol = (tid & 31) * 4;

    if (tid < 128) {
        int p = m0 + tid;
        int v = cil[p];
        sv[tid] = v;
        sw[tid] = inv[v];
        ss[tid] = cin[p];
    }
    __syncthreads();

    float acc[8][8];
#pragma unroll
    for (int i = 0; i < 8; ++i)
#pragma unroll
        for (int j = 0; j < 8; ++j) acc[i][j] = 0.f;

    float4 aReg, bReg;
    // ---- stage 1: K = 256 (32 chunks) ----
    aReg = *(const float4*)(g_identity + (size_t)sv[arow] * CD + acol);
    bReg = *(const float4*)(Wo1 + brow * CD + bcol);
    As[0][acol + 0][arow] = aReg.x; As[0][acol + 1][arow] = aReg.y;
    As[0][acol + 2][arow] = aReg.z; As[0][acol + 3][arow] = aReg.w;
    *(float4*)&Bs[0][brow][bcol] = bReg;
    __syncthreads();

    for (int c = 0; c < 32; ++c) {
        const int cur = c & 1;
        if (c + 1 < 32) {
            int gcol = (c + 1) * 8 + acol;
            const float* base; int src, col;
            if (gcol < 128) { base = g_identity; src = sv[arow]; col = gcol; }
            else            { base = g_hm;       src = sw[arow]; col = gcol - 128; }
            aReg = *(const float4*)(base + (size_t)src * CD + col);
            bReg = *(const float4*)(Wo1 + ((c + 1) * 8 + brow) * CD + bcol);
        }
        gemm8(As[cur], Bs[cur], tx, ty, acc);
        if (c + 1 < 32) {
            const int nb = cur ^ 1;
            As[nb][acol + 0][arow] = aReg.x; As[nb][acol + 1][arow] = aReg.y;
            As[nb][acol + 2][arow] = aReg.z; As[nb][acol + 3][arow] = aReg.w;
            *(float4*)&Bs[nb][brow][bcol] = bReg;
        }
        __syncthreads();
    }

    // ---- epilogue 1: H -> SMEM, reset acc ----
    {
        float bb[8];
#pragma unroll
        for (int j = 0; j < 8; ++j) bb[j] = bo1[tx * 8 + j];
#pragma unroll
        for (int i = 0; i < 8; ++i) {
            int mr = ty * 8 + i;
            float o[8];
#pragma unroll
            for (int j = 0; j < 8; ++j) { o[j] = lrelu(acc[i][j] + bb[j]); acc[i][j] = 0.f; }
            *(float4*)&Hs[mr][tx * 8]     = make_float4(o[0], o[1], o[2], o[3]);
            *(float4*)&Hs[mr][tx * 8 + 4] = make_float4(o[4], o[5], o[6], o[7]);
        }
    }
    bReg = *(const float4*)(Wo2 + brow * CD + bcol);
    *(float4*)&Bs[0][brow][bcol] = bReg;   // distinct buffer from stage-1's last (cur=1)
    __syncthreads();

    // ---- stage 2: K = 128 (16 chunks), A resident in Hs ----
    for (int c = 0; c < 16; ++c) {
        const int cur = c & 1;
        if (c + 1 < 16)
            bReg = *(const float4*)(Wo2 + ((c + 1) * 8 + brow) * CD + bcol);
#pragma unroll
        for (int k = 0; k < 8; ++k) {
            const int kk = c * 8 + k;
            float av[8];
#pragma unroll
            for (int i = 0; i < 8; ++i) av[i] = Hs[ty * 8 + i][kk];
            float4 b0 = *(const float4*)&Bs[cur][k][tx * 8];
            float4 b1 = *(const float4*)&Bs[cur][k][tx * 8 + 4];
            float bv[8] = {b0.x, b0.y, b0.z, b0.w, b1.x, b1.y, b1.z, b1.w};
#pragma unroll
            for (int i = 0; i < 8; ++i)
#pragma unroll
                for (int j = 0; j < 8; ++j)
                    acc[i][j] += av[i] * bv[j];
        }
        if (c + 1 < 16)
            *(float4*)&Bs[cur ^ 1][brow][bcol] = bReg;
        __syncthreads();
    }

    // ---- epilogue 2: Y -> segment sums (vector reductions) ----
    {
        float bb[8];
#pragma unroll
        for (int j = 0; j < 8; ++j) bb[j] = bo2[tx * 8 + j];
#pragma unroll
        for (int i = 0; i < 8; ++i) {
            int seg = ss[ty * 8 + i];
            float o[8];
#pragma unroll
            for (int j = 0; j < 8; ++j) o[j] = acc[i][j] + bb[j];
            red_add_v4(g_pfea + (size_t)seg * CD + tx * 8,     make_float4(o[0], o[1], o[2], o[3]));
            red_add_v4(g_pfea + (size_t)seg * CD + tx * 8 + 4, make_float4(o[4], o[5], o[6], o[7]));
        }
    }
}

// ---------------- out[p] = pfea_sum[cin[p]] / max(cnt,1) ----------------
__global__ void k_gather(const int* __restrict__ cin, float* __restrict__ out) {
    int idx = blockIdx.x * blockDim.x + threadIdx.x;   // NPTS*32 float4 lanes
    if (idx >= NPTS * 32) return;
    int p = idx >> 5;
    int c = (idx & 31) * 4;
    int s = cin[p];
    float ic = 1.0f / fmaxf(g_cntv2[s], 1.0f);
    float4 v = *(const float4*)(g_pfea + (size_t)s * CD + c);
    *(float4*)(out + (size_t)p * CD + c) = make_float4(v.x * ic, v.y * ic, v.z * ic, v.w * ic);
}

// ---------------- launch ----------------
extern "C" void kernel_launch(void* const* d_in, const int* in_sizes, int n_in,
                              void* d_out, int out_size) {
    const float* feat = (const float*)d_in[0];
    const float* vfea = (const float*)d_in[1];
    const int*   inv  = (const int*)d_in[2];
    const int*   cil  = (const int*)d_in[3];
    const int*   cin  = (const int*)d_in[4];
    const float* W_in = (const float*)d_in[5];
    const float* b_in = (const float*)d_in[6];
    const float* W1   = (const float*)d_in[7];
    const float* b1   = (const float*)d_in[8];
    const float* g1   = (const float*)d_in[9];
    const float* be1  = (const float*)d_in[10];
    const float* W2   = (const float*)d_in[11];
    const float* b2   = (const float*)d_in[12];
    const float* g2   = (const float*)d_in[13];
    const float* be2  = (const float*)d_in[14];
    const float* W3   = (const float*)d_in[15];
    const float* b3   = (const float*)d_in[16];
    const float* Wo1  = (const float*)d_in[17];
    const float* bo1  = (const float*)d_in[18];
    const float* Wo2  = (const float*)d_in[19];
    const float* bo2  = (const float*)d_in[20];
    float* out = (float*)d_out;

    const int PTS_SMEM = 21376 * 4;   // 85504 B dynamic SMEM for k_points
    cudaFuncSetAttribute(k_points, cudaFuncAttributeMaxDynamicSharedMemorySize, PTS_SMEM);

    k_zero<<<2048, 256>>>();
    k_counts<<<(NPTS + 255) / 256, 256>>>(inv, cin);
    k_identity<<<(NV + 127) / 128, 256>>>(feat, vfea, inv, W_in, b_in);
    k_mlp1<<<512, 64>>>(W1, b1);
    k_mlp2<<<512, 64>>>(g1, be1, W2, b2);
    k_mlp3<<<512, 128>>>(g2, be2, W3, b3);
    k_points<<<NPTS / 128, 256, PTS_SMEM>>>(cil, cin, inv, Wo1, bo1, Wo2, bo2);
    k_gather<<<(NPTS * 32) / 256, 256>>>(cin, out);
}

// round 2
// speedup vs baseline: 2.5631x; 2.5631x over previous
#include <cuda_runtime.h>
#include <cuda_fp16.h>

#define NV   120000
#define ND   30000
#define NV2  60000
#define NPTS 400000
#define CD   128
#define HD   64

// ---------------- scratch (static device globals; no allocation) ----------------
__device__ float  g_ds[ND * CD];          // segment sums of x
__device__ float  g_cntd[ND];
__device__ __half g_idh[NV * CD];         // identity, f16
__device__ float  g_t1[ND * HD];
__device__ float  g_t2[ND * HD];
__device__ __half g_hmh[ND * CD];         // hm, f16
__device__ float  g_pfea[NV2 * CD];       // segment sums of pts
__device__ float  g_cntv2[NV2];
__device__ float  g_stats[512];           // [0:64) sum1 [128:192) sq1 [256:320) sum2 [384:448) sq2
__device__ __half g_W1h[CD * 256];        // Wo1^T as [n=128][k=256] f16
__device__ __half g_W2h[CD * CD];         // Wo2^T as [n=128][k=128] f16

__device__ __forceinline__ float lrelu(float x) { return x > 0.f ? x : 0.1f * x; }

__device__ __forceinline__ void red_add_v4(float* p, float4 v) {
    asm volatile("red.global.add.v4.f32 [%0], {%1,%2,%3,%4};"
                 :: "l"(p), "f"(v.x), "f"(v.y), "f"(v.z), "f"(v.w) : "memory");
}
__device__ __forceinline__ void red_add_v2(float* p, float a, float b) {
    asm volatile("red.global.add.v2.f32 [%0], {%1,%2};"
                 :: "l"(p), "f"(a), "f"(b) : "memory");
}
__device__ __forceinline__ void mma16816(float* c, const unsigned* a, const unsigned* b) {
    asm volatile("mma.sync.aligned.m16n8k16.row.col.f32.f16.f16.f32 "
                 "{%0,%1,%2,%3},{%4,%5,%6,%7},{%8,%9},{%0,%1,%2,%3};"
                 : "+f"(c[0]), "+f"(c[1]), "+f"(c[2]), "+f"(c[3])
                 : "r"(a[0]), "r"(a[1]), "r"(a[2]), "r"(a[3]), "r"(b[0]), "r"(b[1]));
}

// ---------------- zero scratch ----------------
__global__ void k_zero() {
    int idx = blockIdx.x * blockDim.x + threadIdx.x;
    int stride = gridDim.x * blockDim.x;
    for (int i = idx; i < ND * CD; i += stride)  g_ds[i] = 0.f;
    for (int i = idx; i < ND; i += stride)       g_cntd[i] = 0.f;
    for (int i = idx; i < NV2 * CD; i += stride) g_pfea[i] = 0.f;
    for (int i = idx; i < NV2; i += stride)      g_cntv2[i] = 0.f;
    for (int i = idx; i < 512; i += stride)      g_stats[i] = 0.f;
}

// ---------------- weight prep: transpose Wo1/Wo2 to [n][k] f16 ----------------
__global__ void k_prep(const float* __restrict__ Wo1, const float* __restrict__ Wo2) {
    int i = blockIdx.x * blockDim.x + threadIdx.x;
    if (i < 256 * 128) {
        int k = i >> 7, n = i & 127;
        g_W1h[n * 256 + k] = __float2half_rn(Wo1[i]);
    }
    if (i < 128 * 128) {
        int k = i >> 7, n = i & 127;
        g_W2h[n * 128 + k] = __float2half_rn(Wo2[i]);
    }
}

// ---------------- segment counts ----------------
__global__ void k_counts(const int* __restrict__ inv, const int* __restrict__ cin) {
    int i = blockIdx.x * blockDim.x + threadIdx.x;
    if (i < NV)   atomicAdd(&g_cntd[inv[i]], 1.0f);
    if (i < NPTS) atomicAdd(&g_cntv2[cin[i]], 1.0f);
}

// ---------------- shared GEMM microkernel: 128x128 tile, BK=8, 8x8/thread ----------------
__device__ __forceinline__ void gemm8(const float (* __restrict__ As)[128],
                                      const float (* __restrict__ Bs)[128],
                                      int tx, int ty, float acc[8][8]) {
#pragma unroll
    for (int k = 0; k < 8; ++k) {
        float4 a0 = *(const float4*)&As[k][ty * 8];
        float4 a1 = *(const float4*)&As[k][ty * 8 + 4];
        float4 b0 = *(const float4*)&Bs[k][tx * 8];
        float4 b1 = *(const float4*)&Bs[k][tx * 8 + 4];
        float av[8] = {a0.x, a0.y, a0.z, a0.w, a1.x, a1.y, a1.z, a1.w};
        float bv[8] = {b0.x, b0.y, b0.z, b0.w, b1.x, b1.y, b1.z, b1.w};
#pragma unroll
        for (int i = 0; i < 8; ++i)
#pragma unroll
            for (int j = 0; j < 8; ++j)
                acc[i][j] += av[i] * bv[j];
    }
}

// ---------------- identity = lrelu((f+v) @ W_in + b_in) -> f16; fused scatter-add of x to g_ds ----------------
__global__ void __launch_bounds__(256) k_identity(
    const float* __restrict__ feat, const float* __restrict__ vfea,
    const int* __restrict__ inv,
    const float* __restrict__ W, const float* __restrict__ bias) {
    __shared__ float As[2][8][128];
    __shared__ float Bs[2][8][128];
    const int tid = threadIdx.x;
    const int tx = tid & 15, ty = tid >> 4;
    const int m0 = blockIdx.x * 128;
    const int arow = tid >> 1;
    const int acol = (tid & 1) * 4;
    const int grow = m0 + arow;
    const bool rvalid = grow < NV;
    const int seg = rvalid ? inv[grow] : 0;
    const int brow = tid >> 5;
    const int bcol = (tid & 31) * 4;

    float acc[8][8];
#pragma unroll
    for (int i = 0; i < 8; ++i)
#pragma unroll
        for (int j = 0; j < 8; ++j) acc[i][j] = 0.f;

    float4 aReg = make_float4(0, 0, 0, 0), bReg;
    if (rvalid) {
        float4 f = *(const float4*)(feat + (size_t)grow * CD + acol);
        float4 v = *(const float4*)(vfea + (size_t)grow * CD + acol);
        aReg = make_float4(f.x + v.x, f.y + v.y, f.z + v.z, f.w + v.w);
        red_add_v4(g_ds + (size_t)seg * CD + acol, aReg);
    }
    bReg = *(const float4*)(W + brow * CD + bcol);
    As[0][acol + 0][arow] = aReg.x; As[0][acol + 1][arow] = aReg.y;
    As[0][acol + 2][arow] = aReg.z; As[0][acol + 3][arow] = aReg.w;
    *(float4*)&Bs[0][brow][bcol] = bReg;
    __syncthreads();

    const int NC = 16;  // K = 128
    for (int c = 0; c < NC; ++c) {
        const int cur = c & 1;
        if (c + 1 < NC) {
            int col = (c + 1) * 8 + acol;
            if (rvalid) {
                float4 f = *(const float4*)(feat + (size_t)grow * CD + col);
                float4 v = *(const float4*)(vfea + (size_t)grow * CD + col);
                aReg = make_float4(f.x + v.x, f.y + v.y, f.z + v.z, f.w + v.w);
                red_add_v4(g_ds + (size_t)seg * CD + col, aReg);
            } else aReg = make_float4(0, 0, 0, 0);
            bReg = *(const float4*)(W + ((c + 1) * 8 + brow) * CD + bcol);
        }
        gemm8(As[cur], Bs[cur], tx, ty, acc);
        if (c + 1 < NC) {
            const int nb = cur ^ 1;
            As[nb][acol + 0][arow] = aReg.x; As[nb][acol + 1][arow] = aReg.y;
            As[nb][acol + 2][arow] = aReg.z; As[nb][acol + 3][arow] = aReg.w;
            *(float4*)&Bs[nb][brow][bcol] = bReg;
        }
        __syncthreads();
    }

    float bb[8];
#pragma unroll
    for (int j = 0; j < 8; ++j) bb[j] = bias[tx * 8 + j];
#pragma unroll
    for (int i = 0; i < 8; ++i) {
        int r = m0 + ty * 8 + i;
        if (r < NV) {
            __half2 h[4];
#pragma unroll
            for (int j = 0; j < 4; ++j)
                h[j] = __floats2half2_rn(lrelu(acc[i][2 * j] + bb[2 * j]),
                                         lrelu(acc[i][2 * j + 1] + bb[2 * j + 1]));
            uint4 u;
            u.x = *(unsigned*)&h[0]; u.y = *(unsigned*)&h[1];
            u.z = *(unsigned*)&h[2]; u.w = *(unsigned*)&h[3];
            *(uint4*)(g_idh + (size_t)r * CD + tx * 8) = u;
        }
    }
}

// ---------------- MLP stage 1: t1 = lrelu((ds/cnt) @ W1 + b1), stats ----------------
__global__ void __launch_bounds__(256) k_mlp1(const float* __restrict__ W, const float* __restrict__ bias) {
    __shared__ float As[2][8][128];  // [k][m]
    __shared__ float Bs[2][8][64];   // [k][n]
    __shared__ float ssum[64], ssq[64];
    const int tid = threadIdx.x;
    if (tid < 64) { ssum[tid] = 0.f; ssq[tid] = 0.f; }
    const int tx = tid & 7, ty = tid >> 3;       // n = tx*8, m = ty*4
    const int m0 = blockIdx.x * 128;
    const int arow = tid >> 1, acol = (tid & 1) * 4;
    const int grow = m0 + arow;
    const bool rv = grow < ND;
    const float ic = rv ? 1.0f / fmaxf(g_cntd[grow], 1.0f) : 0.f;
    const int brow = tid >> 4, bcol = (tid & 15) * 4;  // tid<128

    float acc[4][8];
#pragma unroll
    for (int i = 0; i < 4; ++i)
#pragma unroll
        for (int j = 0; j < 8; ++j) acc[i][j] = 0.f;

    float4 aR = make_float4(0, 0, 0, 0), bR = make_float4(0, 0, 0, 0);
    if (rv) {
        float4 t = *(const float4*)(g_ds + (size_t)grow * CD + acol);
        aR = make_float4(t.x * ic, t.y * ic, t.z * ic, t.w * ic);
    }
    if (tid < 128) bR = *(const float4*)(W + brow * 64 + bcol);
    As[0][acol + 0][arow] = aR.x; As[0][acol + 1][arow] = aR.y;
    As[0][acol + 2][arow] = aR.z; As[0][acol + 3][arow] = aR.w;
    if (tid < 128) *(float4*)&Bs[0][brow][bcol] = bR;
    __syncthreads();

    for (int c = 0; c < 16; ++c) {
        const int cur = c & 1;
        if (c + 1 < 16) {
            if (rv) {
                float4 t = *(const float4*)(g_ds + (size_t)grow * CD + (c + 1) * 8 + acol);
                aR = make_float4(t.x * ic, t.y * ic, t.z * ic, t.w * ic);
            }
            if (tid < 128) bR = *(const float4*)(W + ((c + 1) * 8 + brow) * 64 + bcol);
        }
#pragma unroll
        for (int k = 0; k < 8; ++k) {
            float4 a = *(const float4*)&As[cur][k][ty * 4];
            float4 b0 = *(const float4*)&Bs[cur][k][tx * 8];
            float4 b1 = *(const float4*)&Bs[cur][k][tx * 8 + 4];
            float av[4] = {a.x, a.y, a.z, a.w};
            float bv[8] = {b0.x, b0.y, b0.z, b0.w, b1.x, b1.y, b1.z, b1.w};
#pragma unroll
            for (int i = 0; i < 4; ++i)
#pragma unroll
                for (int j = 0; j < 8; ++j)
                    acc[i][j] += av[i] * bv[j];
        }
        if (c + 1 < 16) {
            const int nb = cur ^ 1;
            As[nb][acol + 0][arow] = aR.x; As[nb][acol + 1][arow] = aR.y;
            As[nb][acol + 2][arow] = aR.z; As[nb][acol + 3][arow] = aR.w;
            if (tid < 128) *(float4*)&Bs[nb][brow][bcol] = bR;
        }
        __syncthreads();
    }

    float bb[8];
#pragma unroll
    for (int j = 0; j < 8; ++j) bb[j] = bias[tx * 8 + j];
    float cs[8], cq[8];
#pragma unroll
    for (int j = 0; j < 8; ++j) { cs[j] = 0.f; cq[j] = 0.f; }
#pragma unroll
    for (int i = 0; i < 4; ++i) {
        int r = m0 + ty * 4 + i;
        if (r < ND) {
            float o[8];
#pragma unroll
            for (int j = 0; j < 8; ++j) {
                o[j] = lrelu(acc[i][j] + bb[j]);
                cs[j] += o[j]; cq[j] += o[j] * o[j];
            }
            *(float4*)(g_t1 + (size_t)r * 64 + tx * 8)     = make_float4(o[0], o[1], o[2], o[3]);
            *(float4*)(g_t1 + (size_t)r * 64 + tx * 8 + 4) = make_float4(o[4], o[5], o[6], o[7]);
        }
    }
#pragma unroll
    for (int j = 0; j < 8; ++j) {
        atomicAdd(&ssum[tx * 8 + j], cs[j]);
        atomicAdd(&ssq[tx * 8 + j], cq[j]);
    }
    __syncthreads();
    if (tid < 64) {
        atomicAdd(&g_stats[tid], ssum[tid]);
        atomicAdd(&g_stats[128 + tid], ssq[tid]);
    }
}

// ---------------- MLP stage 2: t2 = lrelu(BN1(t1) @ W2 + b2), stats ----------------
__global__ void __launch_bounds__(256) k_mlp2(const float* __restrict__ gam, const float* __restrict__ bet,
                                              const float* __restrict__ W, const float* __restrict__ bias) {
    __shared__ float As[2][8][128];
    __shared__ float Bs[2][8][64];
    __shared__ float amul[64], aadd[64];
    __shared__ float ssum[64], ssq[64];
    const int tid = threadIdx.x;
    if (tid < 64) {
        const float im = 1.0f / (float)ND;
        float m = g_stats[tid] * im;
        float v = g_stats[128 + tid] * im - m * m;
        float gm = rsqrtf(v + 1e-5f) * gam[tid];
        amul[tid] = gm; aadd[tid] = bet[tid] - m * gm;
        ssum[tid] = 0.f; ssq[tid] = 0.f;
    }
    __syncthreads();
    const int tx = tid & 7, ty = tid >> 3;
    const int m0 = blockIdx.x * 128;
    const int arow = tid >> 1, acol = (tid & 1) * 4;
    const int grow = m0 + arow;
    const bool rv = grow < ND;
    const int brow = tid >> 4, bcol = (tid & 15) * 4;

    float acc[4][8];
#pragma unroll
    for (int i = 0; i < 4; ++i)
#pragma unroll
        for (int j = 0; j < 8; ++j) acc[i][j] = 0.f;

    float4 aR = make_float4(0, 0, 0, 0), bR = make_float4(0, 0, 0, 0);
    if (rv) {
        float4 t = *(const float4*)(g_t1 + (size_t)grow * 64 + acol);
        float4 mm = *(const float4*)&amul[acol];
        float4 ad = *(const float4*)&aadd[acol];
        aR = make_float4(t.x * mm.x + ad.x, t.y * mm.y + ad.y, t.z * mm.z + ad.z, t.w * mm.w + ad.w);
    }
    if (tid < 128) bR = *(const float4*)(W + brow * 64 + bcol);
    As[0][acol + 0][arow] = aR.x; As[0][acol + 1][arow] = aR.y;
    As[0][acol + 2][arow] = aR.z; As[0][acol + 3][arow] = aR.w;
    if (tid < 128) *(float4*)&Bs[0][brow][bcol] = bR;
    __syncthreads();

    for (int c = 0; c < 8; ++c) {
        const int cur = c & 1;
        if (c + 1 < 8) {
            if (rv) {
                int col = (c + 1) * 8 + acol;
                float4 t = *(const float4*)(g_t1 + (size_t)grow * 64 + col);
                float4 mm = *(const float4*)&amul[col];
                float4 ad = *(const float4*)&aadd[col];
                aR = make_float4(t.x * mm.x + ad.x, t.y * mm.y + ad.y, t.z * mm.z + ad.z, t.w * mm.w + ad.w);
            }
            if (tid < 128) bR = *(const float4*)(W + ((c + 1) * 8 + brow) * 64 + bcol);
        }
#pragma unroll
        for (int k = 0; k < 8; ++k) {
            float4 a = *(const float4*)&As[cur][k][ty * 4];
            float4 b0 = *(const float4*)&Bs[cur][k][tx * 8];
            float4 b1 = *(const float4*)&Bs[cur][k][tx * 8 + 4];
            float av[4] = {a.x, a.y, a.z, a.w};
            float bv[8] = {b0.x, b0.y, b0.z, b0.w, b1.x, b1.y, b1.z, b1.w};
#pragma unroll
            for (int i = 0; i < 4; ++i)
#pragma unroll
                for (int j = 0; j < 8; ++j)
                    acc[i][j] += av[i] * bv[j];
        }
        if (c + 1 < 8) {
            const int nb = cur ^ 1;
            As[nb][acol + 0][arow] = aR.x; As[nb][acol + 1][arow] = aR.y;
            As[nb][acol + 2][arow] = aR.z; As[nb][acol + 3][arow] = aR.w;
            if (tid < 128) *(float4*)&Bs[nb][brow][bcol] = bR;
        }
        __syncthreads();
    }

    float bb[8];
#pragma unroll
    for (int j = 0; j < 8; ++j) bb[j] = bias[tx * 8 + j];
    float cs[8], cq[8];
#pragma unroll
    for (int j = 0; j < 8; ++j) { cs[j] = 0.f; cq[j] = 0.f; }
#pragma unroll
    for (int i = 0; i < 4; ++i) {
        int r = m0 + ty * 4 + i;
        if (r < ND) {
            float o[8];
#pragma unroll
            for (int j = 0; j < 8; ++j) {
                o[j] = lrelu(acc[i][j] + bb[j]);
                cs[j] += o[j]; cq[j] += o[j] * o[j];
            }
            *(float4*)(g_t2 + (size_t)r * 64 + tx * 8)     = make_float4(o[0], o[1], o[2], o[3]);
            *(float4*)(g_t2 + (size_t)r * 64 + tx * 8 + 4) = make_float4(o[4], o[5], o[6], o[7]);
        }
    }
#pragma unroll
    for (int j = 0; j < 8; ++j) {
        atomicAdd(&ssum[tx * 8 + j], cs[j]);
        atomicAdd(&ssq[tx * 8 + j], cq[j]);
    }
    __syncthreads();
    if (tid < 64) {
        atomicAdd(&g_stats[256 + tid], ssum[tid]);
        atomicAdd(&g_stats[384 + tid], ssq[tid]);
    }
}

// ---------------- MLP stage 3: hm = lrelu(BN2(t2) @ W3 + b3) -> f16 ----------------
__global__ void __launch_bounds__(256) k_mlp3(const float* __restrict__ gam, const float* __restrict__ bet,
                                              const float* __restrict__ W, const float* __restrict__ bias) {
    __shared__ float As[2][8][128];
    __shared__ float Bs[2][8][128];
    __shared__ float amul[64], aadd[64];
    const int tid = threadIdx.x;
    if (tid < 64) {
        const float im = 1.0f / (float)ND;
        float m = g_stats[256 + tid] * im;
        float v = g_stats[384 + tid] * im - m * m;
        float gm = rsqrtf(v + 1e-5f) * gam[tid];
        amul[tid] = gm; aadd[tid] = bet[tid] - m * gm;
    }
    __syncthreads();
    const int tx = tid & 15, ty = tid >> 4;
    const int m0 = blockIdx.x * 128;
    const int arow = tid >> 1, acol = (tid & 1) * 4;
    const int grow = m0 + arow;
    const bool rv = grow < ND;
    const int brow = tid >> 5, bcol = (tid & 31) * 4;

    float acc[8][8];
#pragma unroll
    for (int i = 0; i < 8; ++i)
#pragma unroll
        for (int j = 0; j < 8; ++j) acc[i][j] = 0.f;

    float4 aR = make_float4(0, 0, 0, 0), bR;
    if (rv) {
        float4 t = *(const float4*)(g_t2 + (size_t)grow * 64 + acol);
        float4 mm = *(const float4*)&amul[acol];
        float4 ad = *(const float4*)&aadd[acol];
        aR = make_float4(t.x * mm.x + ad.x, t.y * mm.y + ad.y, t.z * mm.z + ad.z, t.w * mm.w + ad.w);
    }
    bR = *(const float4*)(W + brow * CD + bcol);
    As[0][acol + 0][arow] = aR.x; As[0][acol + 1][arow] = aR.y;
    As[0][acol + 2][arow] = aR.z; As[0][acol + 3][arow] = aR.w;
    *(float4*)&Bs[0][brow][bcol] = bR;
    __syncthreads();

    for (int c = 0; c < 8; ++c) {
        const int cur = c & 1;
        if (c + 1 < 8) {
            if (rv) {
                int col = (c + 1) * 8 + acol;
                float4 t = *(const float4*)(g_t2 + (size_t)grow * 64 + col);
                float4 mm = *(const float4*)&amul[col];
                float4 ad = *(const float4*)&aadd[col];
                aR = make_float4(t.x * mm.x + ad.x, t.y * mm.y + ad.y, t.z * mm.z + ad.z, t.w * mm.w + ad.w);
            } else aR = make_float4(0, 0, 0, 0);
            bR = *(const float4*)(W + ((c + 1) * 8 + brow) * CD + bcol);
        }
        gemm8(As[cur], Bs[cur], tx, ty, acc);
        if (c + 1 < 8) {
            const int nb = cur ^ 1;
            As[nb][acol + 0][arow] = aR.x; As[nb][acol + 1][arow] = aR.y;
            As[nb][acol + 2][arow] = aR.z; As[nb][acol + 3][arow] = aR.w;
            *(float4*)&Bs[nb][brow][bcol] = bR;
        }
        __syncthreads();
    }

    float bb[8];
#pragma unroll
    for (int j = 0; j < 8; ++j) bb[j] = bias[tx * 8 + j];
#pragma unroll
    for (int i = 0; i < 8; ++i) {
        int r = m0 + ty * 8 + i;
        if (r < ND) {
            __half2 h[4];
#pragma unroll
            for (int j = 0; j < 4; ++j)
                h[j] = __floats2half2_rn(lrelu(acc[i][2 * j] + bb[2 * j]),
                                         lrelu(acc[i][2 * j + 1] + bb[2 * j + 1]));
            uint4 u;
            u.x = *(unsigned*)&h[0]; u.y = *(unsigned*)&h[1];
            u.z = *(unsigned*)&h[2]; u.w = *(unsigned*)&h[3];
            *(uint4*)(g_hmh + (size_t)r * CD + tx * 8) = u;
        }
    }
}

// ---------------- fused point path, f16 tensor-core MMA ----------------
// A[p] = [identity[cil[p]] | hm[inv[cil[p]]]] (f16 gather, K=256)
// H = lrelu(A @ Wo1 + bo1) -> SMEM f16 ; Y = H @ Wo2 + bo2 -> red-add to g_pfea[cin[p]]
__global__ void __launch_bounds__(256, 2) k_points(
    const int* __restrict__ cil, const int* __restrict__ cin, const int* __restrict__ inv,
    const float* __restrict__ bo1, const float* __restrict__ bo2) {
    extern __shared__ __align__(16) char smp[];
    __half (*Asm)[128][24] = (__half (*)[128][24])smp;                 // 2*128*24*2 = 12288 B
    __half (*Bsm)[128][24] = (__half (*)[128][24])(smp + 12288);       // 12288 B
    __half (*Hs)[136]      = (__half (*)[136])(smp + 24576);           // 128*136*2 = 34816 B
    int* sv = (int*)(smp + 59392);
    int* sw = sv + 128;
    int* ss = sw + 128;

    const int tid  = threadIdx.x;
    const int lane = tid & 31;
    const int w    = tid >> 5;
    const int wm   = w & 1;        // M half (0/1) -> rows wm*64 ..
    const int wn   = w >> 1;       // N quarter    -> cols wn*32 ..
    const int g    = lane >> 2;
    const int tg   = lane & 3;
    const int m0   = blockIdx.x * 128;   // NPTS % 128 == 0

    if (tid < 128) {
        int p = m0 + tid;
        int v = cil[p];
        sv[tid] = v;
        sw[tid] = inv[v];
        ss[tid] = cin[p];
    }
    __syncthreads();

    const int row  = tid >> 1;
    const int half = tid & 1;
    const __half* pid = g_idh + (size_t)sv[row] * CD + half * 8;
    const __half* phm = g_hmh + (size_t)sw[row] * CD + half * 8;

    float acc[4][4][4];
#pragma unroll
    for (int a = 0; a < 4; ++a)
#pragma unroll
        for (int b = 0; b < 4; ++b)
#pragma unroll
            for (int c = 0; c < 4; ++c) acc[a][b][c] = 0.f;

    uint4 aR, bR;
    aR = *(const uint4*)pid;
    bR = *(const uint4*)(g_W1h + (size_t)row * 256 + half * 8);
    *(uint4*)&Asm[0][row][half * 8] = aR;
    *(uint4*)&Bsm[0][row][half * 8] = bR;
    __syncthreads();

    // ---- stage 1: K = 256 (16 chunks of 16) ----
    for (int c = 0; c < 16; ++c) {
        const int cur = c & 1;
        if (c < 15) {
            const __half* asrc = (c + 1 < 8) ? (pid + (c + 1) * 16) : (phm + (c + 1 - 8) * 16);
            aR = *(const uint4*)asrc;
            bR = *(const uint4*)(g_W1h + (size_t)row * 256 + (c + 1) * 16 + half * 8);
        }
        unsigned af[4][4], bf[4][2];
#pragma unroll
        for (int mf = 0; mf < 4; ++mf) {
            int r0 = wm * 64 + mf * 16 + g;
            af[mf][0] = *(const unsigned*)&Asm[cur][r0][tg * 2];
            af[mf][1] = *(const unsigned*)&Asm[cur][r0 + 8][tg * 2];
            af[mf][2] = *(const unsigned*)&Asm[cur][r0][tg * 2 + 8];
            af[mf][3] = *(const unsigned*)&Asm[cur][r0 + 8][tg * 2 + 8];
        }
#pragma unroll
        for (int nf = 0; nf < 4; ++nf) {
            int n = wn * 32 + nf * 8 + g;
            bf[nf][0] = *(const unsigned*)&Bsm[cur][n][tg * 2];
            bf[nf][1] = *(const unsigned*)&Bsm[cur][n][tg * 2 + 8];
        }
#pragma unroll
        for (int mf = 0; mf < 4; ++mf)
#pragma unroll
            for (int nf = 0; nf < 4; ++nf)
                mma16816(acc[mf][nf], af[mf], bf[nf]);
        if (c < 15) {
            const int nb = cur ^ 1;
            *(uint4*)&Asm[nb][row][half * 8] = aR;
            *(uint4*)&Bsm[nb][row][half * 8] = bR;
        }
        __syncthreads();
    }

    // ---- epilogue 1: H -> SMEM f16, reset acc ----
#pragma unroll
    for (int mf = 0; mf < 4; ++mf) {
        int r0 = wm * 64 + mf * 16 + g;
#pragma unroll
        for (int nf = 0; nf < 4; ++nf) {
            int col = wn * 32 + nf * 8 + tg * 2;
            float b0 = bo1[col], b1v = bo1[col + 1];
            float* cc = acc[mf][nf];
            __half2 h01 = __floats2half2_rn(lrelu(cc[0] + b0), lrelu(cc[1] + b1v));
            __half2 h23 = __floats2half2_rn(lrelu(cc[2] + b0), lrelu(cc[3] + b1v));
            *(__half2*)&Hs[r0][col]     = h01;
            *(__half2*)&Hs[r0 + 8][col] = h23;
            cc[0] = cc[1] = cc[2] = cc[3] = 0.f;
        }
    }
    bR = *(const uint4*)(g_W2h + (size_t)row * 128 + half * 8);
    *(uint4*)&Bsm[0][row][half * 8] = bR;
    __syncthreads();

    // ---- stage 2: K = 128 (8 chunks of 16), A resident in Hs ----
    for (int c = 0; c < 8; ++c) {
        const int cur = c & 1;
        if (c < 7)
            bR = *(const uint4*)(g_W2h + (size_t)row * 128 + (c + 1) * 16 + half * 8);
        unsigned af[4][4], bf[4][2];
#pragma unroll
        for (int mf = 0; mf < 4; ++mf) {
            int r0 = wm * 64 + mf * 16 + g;
            af[mf][0] = *(const unsigned*)&Hs[r0][c * 16 + tg * 2];
            af[mf][1] = *(const unsigned*)&Hs[r0 + 8][c * 16 + tg * 2];
            af[mf][2] = *(const unsigned*)&Hs[r0][c * 16 + tg * 2 + 8];
            af[mf][3] = *(const unsigned*)&Hs[r0 + 8][c * 16 + tg * 2 + 8];
        }
#pragma unroll
        for (int nf = 0; nf < 4; ++nf) {
            int n = wn * 32 + nf * 8 + g;
            bf[nf][0] = *(const unsigned*)&Bsm[cur][n][tg * 2];
            bf[nf][1] = *(const unsigned*)&Bsm[cur][n][tg * 2 + 8];
        }
#pragma unroll
        for (int mf = 0; mf < 4; ++mf)
#pragma unroll
            for (int nf = 0; nf < 4; ++nf)
                mma16816(acc[mf][nf], af[mf], bf[nf]);
        if (c < 7)
            *(uint4*)&Bsm[cur ^ 1][row][half * 8] = bR;
        __syncthreads();
    }

    // ---- epilogue 2: Y -> segment sums (v2 reductions) ----
#pragma unroll
    for (int mf = 0; mf < 4; ++mf) {
        int r0 = wm * 64 + mf * 16 + g;
        int s0 = ss[r0], s1 = ss[r0 + 8];
#pragma unroll
        for (int nf = 0; nf < 4; ++nf) {
            int col = wn * 32 + nf * 8 + tg * 2;
            float b0 = bo2[col], b1v = bo2[col + 1];
            float* cc = acc[mf][nf];
            red_add_v2(g_pfea + (size_t)s0 * CD + col, cc[0] + b0, cc[1] + b1v);
            red_add_v2(g_pfea + (size_t)s1 * CD + col, cc[2] + b0, cc[3] + b1v);
        }
    }
}

// ---------------- out[p] = pfea_sum[cin[p]] / max(cnt,1) ----------------
__global__ void k_gather(const int* __restrict__ cin, float* __restrict__ out) {
    int idx = blockIdx.x * blockDim.x + threadIdx.x;
    if (idx >= NPTS * 32) return;
    int p = idx >> 5;
    int c = (idx & 31) * 4;
    int s = cin[p];
    float ic = 1.0f / fmaxf(g_cntv2[s], 1.0f);
    float4 v = *(const float4*)(g_pfea + (size_t)s * CD + c);
    *(float4*)(out + (size_t)p * CD + c) = make_float4(v.x * ic, v.y * ic, v.z * ic, v.w * ic);
}

// ---------------- launch ----------------
extern "C" void kernel_launch(void* const* d_in, const int* in_sizes, int n_in,
                              void* d_out, int out_size) {
    const float* feat = (const float*)d_in[0];
    const float* vfea = (const float*)d_in[1];
    const int*   inv  = (const int*)d_in[2];
    const int*   cil  = (const int*)d_in[3];
    const int*   cin  = (const int*)d_in[4];
    const float* W_in = (const float*)d_in[5];
    const float* b_in = (const float*)d_in[6];
    const float* W1   = (const float*)d_in[7];
    const float* b1   = (const float*)d_in[8];
    const float* g1   = (const float*)d_in[9];
    const float* be1  = (const float*)d_in[10];
    const float* W2   = (const float*)d_in[11];
    const float* b2   = (const float*)d_in[12];
    const float* g2   = (const float*)d_in[13];
    const float* be2  = (const float*)d_in[14];
    const float* W3   = (const float*)d_in[15];
    const float* b3   = (const float*)d_in[16];
    const float* Wo1  = (const float*)d_in[17];
    const float* bo1  = (const float*)d_in[18];
    const float* Wo2  = (const float*)d_in[19];
    const float* bo2  = (const float*)d_in[20];
    float* out = (float*)d_out;

    const int PTS_SMEM = 60928;
    cudaFuncSetAttribute(k_points, cudaFuncAttributeMaxDynamicSharedMemorySize, PTS_SMEM);

    k_zero<<<2048, 256>>>();
    k_prep<<<128, 256>>>(Wo1, Wo2);
    k_counts<<<(NPTS + 255) / 256, 256>>>(inv, cin);
    k_identity<<<(NV + 127) / 128, 256>>>(feat, vfea, inv, W_in, b_in);
    k_mlp1<<<(ND + 127) / 128, 256>>>(W1, b1);
    k_mlp2<<<(ND + 127) / 128, 256>>>(g1, be1, W2, b2);
    k_mlp3<<<(ND + 127) / 128, 256>>>(g2, be2, W3, b3);
    k_points<<<NPTS / 128, 256, PTS_SMEM>>>(cil, cin, inv, bo1, bo2);
    k_gather<<<(NPTS * 32) / 256, 256>>>(cin, out);
}

// round 3
// speedup vs baseline: 2.9128x; 1.1364x over previous
#include <cuda_runtime.h>
#include <cuda_fp16.h>

#define NV   120000
#define ND   30000
#define NV2  60000
#define NPTS 400000
#define CD   128
#define HD   64

// ---------------- scratch (static device globals; no allocation) ----------------
__device__ float  g_ds[ND * CD];          // segment sums of x
__device__ float  g_cntd[ND];
__device__ __half g_idh[NV * CD];         // identity, f16
__device__ float  g_t1[ND * HD];
__device__ float  g_t2[ND * HD];
__device__ __half g_hmh[ND * CD];         // hm, f16
__device__ float  g_pfea[NV2 * CD];       // segment sums of pts
__device__ float  g_cntv2[NV2];
__device__ float  g_stats[512];           // [0:64) sum1 [128:192) sq1 [256:320) sum2 [384:448) sq2
__device__ __half g_W1h[CD * 256];        // Wo1^T as [n=128][k=256] f16
__device__ __half g_W2h[CD * CD];         // Wo2^T as [n=128][k=128] f16
__device__ __half g_Winh[CD * CD];        // W_in^T as [n=128][k=128] f16

__device__ __forceinline__ float lrelu(float x) { return x > 0.f ? x : 0.1f * x; }

__device__ __forceinline__ void red_add_v4(float* p, float4 v) {
    asm volatile("red.global.add.v4.f32 [%0], {%1,%2,%3,%4};"
                 :: "l"(p), "f"(v.x), "f"(v.y), "f"(v.z), "f"(v.w) : "memory");
}
__device__ __forceinline__ void red_add_v2(float* p, float a, float b) {
    asm volatile("red.global.add.v2.f32 [%0], {%1,%2};"
                 :: "l"(p), "f"(a), "f"(b) : "memory");
}
__device__ __forceinline__ void mma16816(float* c, const unsigned* a, const unsigned* b) {
    asm volatile("mma.sync.aligned.m16n8k16.row.col.f32.f16.f16.f32 "
                 "{%0,%1,%2,%3},{%4,%5,%6,%7},{%8,%9},{%0,%1,%2,%3};"
                 : "+f"(c[0]), "+f"(c[1]), "+f"(c[2]), "+f"(c[3])
                 : "r"(a[0]), "r"(a[1]), "r"(a[2]), "r"(a[3]), "r"(b[0]), "r"(b[1]));
}

// ---------------- zero scratch ----------------
__global__ void k_zero() {
    int idx = blockIdx.x * blockDim.x + threadIdx.x;
    int stride = gridDim.x * blockDim.x;
    for (int i = idx; i < ND * CD; i += stride)  g_ds[i] = 0.f;
    for (int i = idx; i < ND; i += stride)       g_cntd[i] = 0.f;
    for (int i = idx; i < NV2 * CD; i += stride) g_pfea[i] = 0.f;
    for (int i = idx; i < NV2; i += stride)      g_cntv2[i] = 0.f;
    for (int i = idx; i < 512; i += stride)      g_stats[i] = 0.f;
}

// ---------------- weight prep: transpose Wo1/Wo2/W_in to [n][k] f16 ----------------
__global__ void k_prep(const float* __restrict__ Wo1, const float* __restrict__ Wo2,
                       const float* __restrict__ Win) {
    int i = blockIdx.x * blockDim.x + threadIdx.x;
    if (i < 256 * 128) {
        int k = i >> 7, n = i & 127;
        g_W1h[n * 256 + k] = __float2half_rn(Wo1[i]);
    }
    if (i < 128 * 128) {
        int k = i >> 7, n = i & 127;
        g_W2h[n * 128 + k]  = __float2half_rn(Wo2[i]);
        g_Winh[n * 128 + k] = __float2half_rn(Win[i]);
    }
}

// ---------------- segment counts ----------------
__global__ void k_counts(const int* __restrict__ inv, const int* __restrict__ cin) {
    int i = blockIdx.x * blockDim.x + threadIdx.x;
    if (i < NV)   atomicAdd(&g_cntd[inv[i]], 1.0f);
    if (i < NPTS) atomicAdd(&g_cntv2[cin[i]], 1.0f);
}

// ---------------- identity = lrelu((f+v) @ W_in + b_in) -> f16 (tensor core);
//                  fused scatter-add of x=f+v into g_ds ----------------
__global__ void __launch_bounds__(256) k_identity(
    const float* __restrict__ feat, const float* __restrict__ vfea,
    const int* __restrict__ inv, const float* __restrict__ bias) {
    extern __shared__ __align__(16) char smi[];
    __half (*Asm)[136] = (__half (*)[136])smi;              // 128*136*2 = 34816 B
    __half (*Bsm)[136] = (__half (*)[136])(smi + 34816);    // 34816 B

    const int tid  = threadIdx.x;
    const int lane = tid & 31;
    const int w    = tid >> 5;
    const int wm   = w & 1;
    const int wn   = w >> 1;
    const int g    = lane >> 2;
    const int tg   = lane & 3;
    const int m0   = blockIdx.x * 128;
    const int row  = tid >> 1;
    const int half = tid & 1;            // cols [half*64, half*64+64)
    const int grow = m0 + row;
    const bool rv  = grow < NV;
    const int seg  = rv ? inv[grow] : 0;

    // ---- load A tile: x = f+v (fp32), red-add to g_ds, f16 into SMEM ----
#pragma unroll
    for (int c = 0; c < 4; ++c) {
        int col = half * 64 + c * 16;
        __half2 h[8];
        if (rv) {
            const float* pf = feat + (size_t)grow * CD + col;
            const float* pv = vfea + (size_t)grow * CD + col;
            float* pd = g_ds + (size_t)seg * CD + col;
#pragma unroll
            for (int q = 0; q < 4; ++q) {
                float4 f = *(const float4*)(pf + q * 4);
                float4 v = *(const float4*)(pv + q * 4);
                float4 x = make_float4(f.x + v.x, f.y + v.y, f.z + v.z, f.w + v.w);
                red_add_v4(pd + q * 4, x);
                h[q * 2]     = __floats2half2_rn(x.x, x.y);
                h[q * 2 + 1] = __floats2half2_rn(x.z, x.w);
            }
        } else {
#pragma unroll
            for (int q = 0; q < 8; ++q) h[q] = __floats2half2_rn(0.f, 0.f);
        }
        uint4 u0, u1;
        u0.x = *(unsigned*)&h[0]; u0.y = *(unsigned*)&h[1];
        u0.z = *(unsigned*)&h[2]; u0.w = *(unsigned*)&h[3];
        u1.x = *(unsigned*)&h[4]; u1.y = *(unsigned*)&h[5];
        u1.z = *(unsigned*)&h[6]; u1.w = *(unsigned*)&h[7];
        *(uint4*)&Asm[row][col]     = u0;
        *(uint4*)&Asm[row][col + 8] = u1;
    }
    // ---- load full B tile (W_in^T f16) ----
#pragma unroll
    for (int j = 0; j < 8; ++j) {
        int col = half * 64 + j * 8;
        *(uint4*)&Bsm[row][col] = *(const uint4*)(g_Winh + (size_t)row * 128 + col);
    }
    __syncthreads();

    // ---- MMA: K=128, 8 chunks, all resident, no intra-loop syncs ----
    float acc[4][4][4];
#pragma unroll
    for (int a = 0; a < 4; ++a)
#pragma unroll
        for (int b = 0; b < 4; ++b)
#pragma unroll
            for (int c = 0; c < 4; ++c) acc[a][b][c] = 0.f;

#pragma unroll
    for (int c = 0; c < 8; ++c) {
        unsigned af[4][4], bf[4][2];
#pragma unroll
        for (int mf = 0; mf < 4; ++mf) {
            int r0 = wm * 64 + mf * 16 + g;
            af[mf][0] = *(const unsigned*)&Asm[r0][c * 16 + tg * 2];
            af[mf][1] = *(const unsigned*)&Asm[r0 + 8][c * 16 + tg * 2];
            af[mf][2] = *(const unsigned*)&Asm[r0][c * 16 + tg * 2 + 8];
            af[mf][3] = *(const unsigned*)&Asm[r0 + 8][c * 16 + tg * 2 + 8];
        }
#pragma unroll
        for (int nf = 0; nf < 4; ++nf) {
            int n = wn * 32 + nf * 8 + g;
            bf[nf][0] = *(const unsigned*)&Bsm[n][c * 16 + tg * 2];
            bf[nf][1] = *(const unsigned*)&Bsm[n][c * 16 + tg * 2 + 8];
        }
#pragma unroll
        for (int mf = 0; mf < 4; ++mf)
#pragma unroll
            for (int nf = 0; nf < 4; ++nf)
                mma16816(acc[mf][nf], af[mf], bf[nf]);
    }
    __syncthreads();   // all reads of Asm done before epilogue overwrites it

    // ---- epilogue: bias+lrelu -> f16 staged in Asm -> coalesced global ----
#pragma unroll
    for (int mf = 0; mf < 4; ++mf) {
        int r0 = wm * 64 + mf * 16 + g;
#pragma unroll
        for (int nf = 0; nf < 4; ++nf) {
            int col = wn * 32 + nf * 8 + tg * 2;
            float b0 = bias[col], b1v = bias[col + 1];
            float* cc = acc[mf][nf];
            *(__half2*)&Asm[r0][col]     = __floats2half2_rn(lrelu(cc[0] + b0), lrelu(cc[1] + b1v));
            *(__half2*)&Asm[r0 + 8][col] = __floats2half2_rn(lrelu(cc[2] + b0), lrelu(cc[3] + b1v));
        }
    }
    __syncthreads();
    if (rv) {
#pragma unroll
        for (int j = 0; j < 8; ++j) {
            int col = half * 64 + j * 8;
            *(uint4*)(g_idh + (size_t)grow * CD + col) = *(const uint4*)&Asm[row][col];
        }
    }
}

// ---------------- MLP stage 1: t1 = lrelu((ds/cnt) @ W1 + b1), stats ----------------
__global__ void __launch_bounds__(256) k_mlp1(const float* __restrict__ W, const float* __restrict__ bias) {
    __shared__ float As[2][8][128];  // [k][m]
    __shared__ float Bs[2][8][64];   // [k][n]
    __shared__ float ssum[64], ssq[64];
    const int tid = threadIdx.x;
    if (tid < 64) { ssum[tid] = 0.f; ssq[tid] = 0.f; }
    const int tx = tid & 7, ty = tid >> 3;       // n = tx*8, m = ty*4
    const int m0 = blockIdx.x * 128;
    const int arow = tid >> 1, acol = (tid & 1) * 4;
    const int grow = m0 + arow;
    const bool rv = grow < ND;
    const float ic = rv ? 1.0f / fmaxf(g_cntd[grow], 1.0f) : 0.f;
    const int brow = tid >> 4, bcol = (tid & 15) * 4;  // tid<128

    float acc[4][8];
#pragma unroll
    for (int i = 0; i < 4; ++i)
#pragma unroll
        for (int j = 0; j < 8; ++j) acc[i][j] = 0.f;

    float4 aR = make_float4(0, 0, 0, 0), bR = make_float4(0, 0, 0, 0);
    if (rv) {
        float4 t = *(const float4*)(g_ds + (size_t)grow * CD + acol);
        aR = make_float4(t.x * ic, t.y * ic, t.z * ic, t.w * ic);
    }
    if (tid < 128) bR = *(const float4*)(W + brow * 64 + bcol);
    As[0][acol + 0][arow] = aR.x; As[0][acol + 1][arow] = aR.y;
    As[0][acol + 2][arow] = aR.z; As[0][acol + 3][arow] = aR.w;
    if (tid < 128) *(float4*)&Bs[0][brow][bcol] = bR;
    __syncthreads();

    for (int c = 0; c < 16; ++c) {
        const int cur = c & 1;
        if (c + 1 < 16) {
            if (rv) {
                float4 t = *(const float4*)(g_ds + (size_t)grow * CD + (c + 1) * 8 + acol);
                aR = make_float4(t.x * ic, t.y * ic, t.z * ic, t.w * ic);
            }
            if (tid < 128) bR = *(const float4*)(W + ((c + 1) * 8 + brow) * 64 + bcol);
        }
#pragma unroll
        for (int k = 0; k < 8; ++k) {
            float4 a = *(const float4*)&As[cur][k][ty * 4];
            float4 b0 = *(const float4*)&Bs[cur][k][tx * 8];
            float4 b1 = *(const float4*)&Bs[cur][k][tx * 8 + 4];
            float av[4] = {a.x, a.y, a.z, a.w};
            float bv[8] = {b0.x, b0.y, b0.z, b0.w, b1.x, b1.y, b1.z, b1.w};
#pragma unroll
            for (int i = 0; i < 4; ++i)
#pragma unroll
                for (int j = 0; j < 8; ++j)
                    acc[i][j] += av[i] * bv[j];
        }
        if (c + 1 < 16) {
            const int nb = cur ^ 1;
            As[nb][acol + 0][arow] = aR.x; As[nb][acol + 1][arow] = aR.y;
            As[nb][acol + 2][arow] = aR.z; As[nb][acol + 3][arow] = aR.w;
            if (tid < 128) *(float4*)&Bs[nb][brow][bcol] = bR;
        }
        __syncthreads();
    }

    float bb[8];
#pragma unroll
    for (int j = 0; j < 8; ++j) bb[j] = bias[tx * 8 + j];
    float cs[8], cq[8];
#pragma unroll
    for (int j = 0; j < 8; ++j) { cs[j] = 0.f; cq[j] = 0.f; }
#pragma unroll
    for (int i = 0; i < 4; ++i) {
        int r = m0 + ty * 4 + i;
        if (r < ND) {
            float o[8];
#pragma unroll
            for (int j = 0; j < 8; ++j) {
                o[j] = lrelu(acc[i][j] + bb[j]);
                cs[j] += o[j]; cq[j] += o[j] * o[j];
            }
            *(float4*)(g_t1 + (size_t)r * 64 + tx * 8)     = make_float4(o[0], o[1], o[2], o[3]);
            *(float4*)(g_t1 + (size_t)r * 64 + tx * 8 + 4) = make_float4(o[4], o[5], o[6], o[7]);
        }
    }
#pragma unroll
    for (int j = 0; j < 8; ++j) {
        atomicAdd(&ssum[tx * 8 + j], cs[j]);
        atomicAdd(&ssq[tx * 8 + j], cq[j]);
    }
    __syncthreads();
    if (tid < 64) {
        atomicAdd(&g_stats[tid], ssum[tid]);
        atomicAdd(&g_stats[128 + tid], ssq[tid]);
    }
}

// ---------------- MLP stage 2: t2 = lrelu(BN1(t1) @ W2 + b2), stats ----------------
__global__ void __launch_bounds__(256) k_mlp2(const float* __restrict__ gam, const float* __restrict__ bet,
                                              const float* __restrict__ W, const float* __restrict__ bias) {
    __shared__ float As[2][8][128];
    __shared__ float Bs[2][8][64];
    __shared__ float amul[64], aadd[64];
    __shared__ float ssum[64], ssq[64];
    const int tid = threadIdx.x;
    if (tid < 64) {
        const float im = 1.0f / (float)ND;
        float m = g_stats[tid] * im;
        float v = g_stats[128 + tid] * im - m * m;
        float gm = rsqrtf(v + 1e-5f) * gam[tid];
        amul[tid] = gm; aadd[tid] = bet[tid] - m * gm;
        ssum[tid] = 0.f; ssq[tid] = 0.f;
    }
    __syncthreads();
    const int tx = tid & 7, ty = tid >> 3;
    const int m0 = blockIdx.x * 128;
    const int arow = tid >> 1, acol = (tid & 1) * 4;
    const int grow = m0 + arow;
    const bool rv = grow < ND;
    const int brow = tid >> 4, bcol = (tid & 15) * 4;

    float acc[4][8];
#pragma unroll
    for (int i = 0; i < 4; ++i)
#pragma unroll
        for (int j = 0; j < 8; ++j) acc[i][j] = 0.f;

    float4 aR = make_float4(0, 0, 0, 0), bR = make_float4(0, 0, 0, 0);
    if (rv) {
        float4 t = *(const float4*)(g_t1 + (size_t)grow * 64 + acol);
        float4 mm = *(const float4*)&amul[acol];
        float4 ad = *(const float4*)&aadd[acol];
        aR = make_float4(t.x * mm.x + ad.x, t.y * mm.y + ad.y, t.z * mm.z + ad.z, t.w * mm.w + ad.w);
    }
    if (tid < 128) bR = *(const float4*)(W + brow * 64 + bcol);
    As[0][acol + 0][arow] = aR.x; As[0][acol + 1][arow] = aR.y;
    As[0][acol + 2][arow] = aR.z; As[0][acol + 3][arow] = aR.w;
    if (tid < 128) *(float4*)&Bs[0][brow][bcol] = bR;
    __syncthreads();

    for (int c = 0; c < 8; ++c) {
        const int cur = c & 1;
        if (c + 1 < 8) {
            if (rv) {
                int col = (c + 1) * 8 + acol;
                float4 t = *(const float4*)(g_t1 + (size_t)grow * 64 + col);
                float4 mm = *(const float4*)&amul[col];
                float4 ad = *(const float4*)&aadd[col];
                aR = make_float4(t.x * mm.x + ad.x, t.y * mm.y + ad.y, t.z * mm.z + ad.z, t.w * mm.w + ad.w);
            }
            if (tid < 128) bR = *(const float4*)(W + ((c + 1) * 8 + brow) * 64 + bcol);
        }
#pragma unroll
        for (int k = 0; k < 8; ++k) {
            float4 a = *(const float4*)&As[cur][k][ty * 4];
            float4 b0 = *(const float4*)&Bs[cur][k][tx * 8];
            float4 b1 = *(const float4*)&Bs[cur][k][tx * 8 + 4];
            float av[4] = {a.x, a.y, a.z, a.w};
            float bv[8] = {b0.x, b0.y, b0.z, b0.w, b1.x, b1.y, b1.z, b1.w};
#pragma unroll
            for (int i = 0; i < 4; ++i)
#pragma unroll
                for (int j = 0; j < 8; ++j)
                    acc[i][j] += av[i] * bv[j];
        }
        if (c + 1 < 8) {
            const int nb = cur ^ 1;
            As[nb][acol + 0][arow] = aR.x; As[nb][acol + 1][arow] = aR.y;
            As[nb][acol + 2][arow] = aR.z; As[nb][acol + 3][arow] = aR.w;
            if (tid < 128) *(float4*)&Bs[nb][brow][bcol] = bR;
        }
        __syncthreads();
    }

    float bb[8];
#pragma unroll
    for (int j = 0; j < 8; ++j) bb[j] = bias[tx * 8 + j];
    float cs[8], cq[8];
#pragma unroll
    for (int j = 0; j < 8; ++j) { cs[j] = 0.f; cq[j] = 0.f; }
#pragma unroll
    for (int i = 0; i < 4; ++i) {
        int r = m0 + ty * 4 + i;
        if (r < ND) {
            float o[8];
#pragma unroll
            for (int j = 0; j < 8; ++j) {
                o[j] = lrelu(acc[i][j] + bb[j]);
                cs[j] += o[j]; cq[j] += o[j] * o[j];
            }
            *(float4*)(g_t2 + (size_t)r * 64 + tx * 8)     = make_float4(o[0], o[1], o[2], o[3]);
            *(float4*)(g_t2 + (size_t)r * 64 + tx * 8 + 4) = make_float4(o[4], o[5], o[6], o[7]);
        }
    }
#pragma unroll
    for (int j = 0; j < 8; ++j) {
        atomicAdd(&ssum[tx * 8 + j], cs[j]);
        atomicAdd(&ssq[tx * 8 + j], cq[j]);
    }
    __syncthreads();
    if (tid < 64) {
        atomicAdd(&g_stats[256 + tid], ssum[tid]);
        atomicAdd(&g_stats[384 + tid], ssq[tid]);
    }
}

// ---------------- MLP stage 3: hm = lrelu(BN2(t2) @ W3 + b3) -> f16 ----------------
__global__ void __launch_bounds__(256) k_mlp3(const float* __restrict__ gam, const float* __restrict__ bet,
                                              const float* __restrict__ W, const float* __restrict__ bias) {
    __shared__ float As[2][8][128];
    __shared__ float Bs[2][8][128];
    __shared__ float amul[64], aadd[64];
    const int tid = threadIdx.x;
    if (tid < 64) {
        const float im = 1.0f / (float)ND;
        float m = g_stats[256 + tid] * im;
        float v = g_stats[384 + tid] * im - m * m;
        float gm = rsqrtf(v + 1e-5f) * gam[tid];
        amul[tid] = gm; aadd[tid] = bet[tid] - m * gm;
    }
    __syncthreads();
    const int tx = tid & 15, ty = tid >> 4;
    const int m0 = blockIdx.x * 128;
    const int arow = tid >> 1, acol = (tid & 1) * 4;
    const int grow = m0 + arow;
    const bool rv = grow < ND;
    const int brow = tid >> 5, bcol = (tid & 31) * 4;

    float acc[8][8];
#pragma unroll
    for (int i = 0; i < 8; ++i)
#pragma unroll
        for (int j = 0; j < 8; ++j) acc[i][j] = 0.f;

    float4 aR = make_float4(0, 0, 0, 0), bR;
    if (rv) {
        float4 t = *(const float4*)(g_t2 + (size_t)grow * 64 + acol);
        float4 mm = *(const float4*)&amul[acol];
        float4 ad = *(const float4*)&aadd[acol];
        aR = make_float4(t.x * mm.x + ad.x, t.y * mm.y + ad.y, t.z * mm.z + ad.z, t.w * mm.w + ad.w);
    }
    bR = *(const float4*)(W + brow * CD + bcol);
    As[0][acol + 0][arow] = aR.x; As[0][acol + 1][arow] = aR.y;
    As[0][acol + 2][arow] = aR.z; As[0][acol + 3][arow] = aR.w;
    *(float4*)&Bs[0][brow][bcol] = bR;
    __syncthreads();

    for (int c = 0; c < 8; ++c) {
        const int cur = c & 1;
        if (c + 1 < 8) {
            if (rv) {
                int col = (c + 1) * 8 + acol;
                float4 t = *(const float4*)(g_t2 + (size_t)grow * 64 + col);
                float4 mm = *(const float4*)&amul[col];
                float4 ad = *(const float4*)&aadd[col];
                aR = make_float4(t.x * mm.x + ad.x, t.y * mm.y + ad.y, t.z * mm.z + ad.z, t.w * mm.w + ad.w);
            } else aR = make_float4(0, 0, 0, 0);
            bR = *(const float4*)(W + ((c + 1) * 8 + brow) * CD + bcol);
        }
#pragma unroll
        for (int k = 0; k < 8; ++k) {
            float4 a0 = *(const float4*)&As[cur][k][ty * 8];
            float4 a1 = *(const float4*)&As[cur][k][ty * 8 + 4];
            float4 b0 = *(const float4*)&Bs[cur][k][tx * 8];
            float4 b1 = *(const float4*)&Bs[cur][k][tx * 8 + 4];
            float av[8] = {a0.x, a0.y, a0.z, a0.w, a1.x, a1.y, a1.z, a1.w};
            float bv[8] = {b0.x, b0.y, b0.z, b0.w, b1.x, b1.y, b1.z, b1.w};
#pragma unroll
            for (int i = 0; i < 8; ++i)
#pragma unroll
                for (int j = 0; j < 8; ++j)
                    acc[i][j] += av[i] * bv[j];
        }
        if (c + 1 < 8) {
            const int nb = cur ^ 1;
            As[nb][acol + 0][arow] = aR.x; As[nb][acol + 1][arow] = aR.y;
            As[nb][acol + 2][arow] = aR.z; As[nb][acol + 3][arow] = aR.w;
            *(float4*)&Bs[nb][brow][bcol] = bR;
        }
        __syncthreads();
    }

    float bb[8];
#pragma unroll
    for (int j = 0; j < 8; ++j) bb[j] = bias[tx * 8 + j];
#pragma unroll
    for (int i = 0; i < 8; ++i) {
        int r = m0 + ty * 8 + i;
        if (r < ND) {
            __half2 h[4];
#pragma unroll
            for (int j = 0; j < 4; ++j)
                h[j] = __floats2half2_rn(lrelu(acc[i][2 * j] + bb[2 * j]),
                                         lrelu(acc[i][2 * j + 1] + bb[2 * j + 1]));
            uint4 u;
            u.x = *(unsigned*)&h[0]; u.y = *(unsigned*)&h[1];
            u.z = *(unsigned*)&h[2]; u.w = *(unsigned*)&h[3];
            *(uint4*)(g_hmh + (size_t)r * CD + tx * 8) = u;
        }
    }
}

// ---------------- fused point path, f16 tensor-core MMA ----------------
__global__ void __launch_bounds__(256, 2) k_points(
    const int* __restrict__ cil, const int* __restrict__ cin, const int* __restrict__ inv,
    const float* __restrict__ bo1, const float* __restrict__ bo2) {
    extern __shared__ __align__(16) char smp[];
    __half (*Asm)[128][24] = (__half (*)[128][24])smp;                 // 12288 B
    __half (*Bsm)[128][24] = (__half (*)[128][24])(smp + 12288);       // 12288 B
    __half (*Hs)[136]      = (__half (*)[136])(smp + 24576);           // 34816 B
    int* sv = (int*)(smp + 59392);
    int* sw = sv + 128;
    int* ss = sw + 128;

    const int tid  = threadIdx.x;
    const int lane = tid & 31;
    const int w    = tid >> 5;
    const int wm   = w & 1;
    const int wn   = w >> 1;
    const int g    = lane >> 2;
    const int tg   = lane & 3;
    const int m0   = blockIdx.x * 128;   // NPTS % 128 == 0

    if (tid < 128) {
        int p = m0 + tid;
        int v = cil[p];
        sv[tid] = v;
        sw[tid] = inv[v];
        ss[tid] = cin[p];
    }
    __syncthreads();

    const int row  = tid >> 1;
    const int half = tid & 1;
    const __half* pid = g_idh + (size_t)sv[row] * CD + half * 8;
    const __half* phm = g_hmh + (size_t)sw[row] * CD + half * 8;

    float acc[4][4][4];
#pragma unroll
    for (int a = 0; a < 4; ++a)
#pragma unroll
        for (int b = 0; b < 4; ++b)
#pragma unroll
            for (int c = 0; c < 4; ++c) acc[a][b][c] = 0.f;

    uint4 aR, bR;
    aR = *(const uint4*)pid;
    bR = *(const uint4*)(g_W1h + (size_t)row * 256 + half * 8);
    *(uint4*)&Asm[0][row][half * 8] = aR;
    *(uint4*)&Bsm[0][row][half * 8] = bR;
    __syncthreads();

    // ---- stage 1: K = 256 (16 chunks of 16) ----
    for (int c = 0; c < 16; ++c) {
        const int cur = c & 1;
        if (c < 15) {
            const __half* asrc = (c + 1 < 8) ? (pid + (c + 1) * 16) : (phm + (c + 1 - 8) * 16);
            aR = *(const uint4*)asrc;
            bR = *(const uint4*)(g_W1h + (size_t)row * 256 + (c + 1) * 16 + half * 8);
        }
        unsigned af[4][4], bf[4][2];
#pragma unroll
        for (int mf = 0; mf < 4; ++mf) {
            int r0 = wm * 64 + mf * 16 + g;
            af[mf][0] = *(const unsigned*)&Asm[cur][r0][tg * 2];
            af[mf][1] = *(const unsigned*)&Asm[cur][r0 + 8][tg * 2];
            af[mf][2] = *(const unsigned*)&Asm[cur][r0][tg * 2 + 8];
            af[mf][3] = *(const unsigned*)&Asm[cur][r0 + 8][tg * 2 + 8];
        }
#pragma unroll
        for (int nf = 0; nf < 4; ++nf) {
            int n = wn * 32 + nf * 8 + g;
            bf[nf][0] = *(const unsigned*)&Bsm[cur][n][tg * 2];
            bf[nf][1] = *(const unsigned*)&Bsm[cur][n][tg * 2 + 8];
        }
#pragma unroll
        for (int mf = 0; mf < 4; ++mf)
#pragma unroll
            for (int nf = 0; nf < 4; ++nf)
                mma16816(acc[mf][nf], af[mf], bf[nf]);
        if (c < 15) {
            const int nb = cur ^ 1;
            *(uint4*)&Asm[nb][row][half * 8] = aR;
            *(uint4*)&Bsm[nb][row][half * 8] = bR;
        }
        __syncthreads();
    }

    // ---- epilogue 1: H -> SMEM f16, reset acc ----
#pragma unroll
    for (int mf = 0; mf < 4; ++mf) {
        int r0 = wm * 64 + mf * 16 + g;
#pragma unroll
        for (int nf = 0; nf < 4; ++nf) {
            int col = wn * 32 + nf * 8 + tg * 2;
            float b0 = bo1[col], b1v = bo1[col + 1];
            float* cc = acc[mf][nf];
            __half2 h01 = __floats2half2_rn(lrelu(cc[0] + b0), lrelu(cc[1] + b1v));
            __half2 h23 = __floats2half2_rn(lrelu(cc[2] + b0), lrelu(cc[3] + b1v));
            *(__half2*)&Hs[r0][col]     = h01;
            *(__half2*)&Hs[r0 + 8][col] = h23;
            cc[0] = cc[1] = cc[2] = cc[3] = 0.f;
        }
    }
    bR = *(const uint4*)(g_W2h + (size_t)row * 128 + half * 8);
    *(uint4*)&Bsm[0][row][half * 8] = bR;
    __syncthreads();

    // ---- stage 2: K = 128 (8 chunks of 16), A resident in Hs ----
    for (int c = 0; c < 8; ++c) {
        const int cur = c & 1;
        if (c < 7)
            bR = *(const uint4*)(g_W2h + (size_t)row * 128 + (c + 1) * 16 + half * 8);
        unsigned af[4][4], bf[4][2];
#pragma unroll
        for (int mf = 0; mf < 4; ++mf) {
            int r0 = wm * 64 + mf * 16 + g;
            af[mf][0] = *(const unsigned*)&Hs[r0][c * 16 + tg * 2];
            af[mf][1] = *(const unsigned*)&Hs[r0 + 8][c * 16 + tg * 2];
            af[mf][2] = *(const unsigned*)&Hs[r0][c * 16 + tg * 2 + 8];
            af[mf][3] = *(const unsigned*)&Hs[r0 + 8][c * 16 + tg * 2 + 8];
        }
#pragma unroll
        for (int nf = 0; nf < 4; ++nf) {
            int n = wn * 32 + nf * 8 + g;
            bf[nf][0] = *(const unsigned*)&Bsm[cur][n][tg * 2];
            bf[nf][1] = *(const unsigned*)&Bsm[cur][n][tg * 2 + 8];
        }
#pragma unroll
        for (int mf = 0; mf < 4; ++mf)
#pragma unroll
            for (int nf = 0; nf < 4; ++nf)
                mma16816(acc[mf][nf], af[mf], bf[nf]);
        if (c < 7)
            *(uint4*)&Bsm[cur ^ 1][row][half * 8] = bR;
        __syncthreads();
    }

    // ---- epilogue 2: Y -> segment sums (v2 reductions) ----
#pragma unroll
    for (int mf = 0; mf < 4; ++mf) {
        int r0 = wm * 64 + mf * 16 + g;
        int s0 = ss[r0], s1 = ss[r0 + 8];
#pragma unroll
        for (int nf = 0; nf < 4; ++nf) {
            int col = wn * 32 + nf * 8 + tg * 2;
            float b0 = bo2[col], b1v = bo2[col + 1];
            float* cc = acc[mf][nf];
            red_add_v2(g_pfea + (size_t)s0 * CD + col, cc[0] + b0, cc[1] + b1v);
            red_add_v2(g_pfea + (size_t)s1 * CD + col, cc[2] + b0, cc[3] + b1v);
        }
    }
}

// ---------------- out[p] = pfea_sum[cin[p]] / max(cnt,1) ----------------
__global__ void k_gather(const int* __restrict__ cin, float* __restrict__ out) {
    int idx = blockIdx.x * blockDim.x + threadIdx.x;
    if (idx >= NPTS * 32) return;
    int p = idx >> 5;
    int c = (idx & 31) * 4;
    int s = cin[p];
    float ic = 1.0f / fmaxf(g_cntv2[s], 1.0f);
    float4 v = *(const float4*)(g_pfea + (size_t)s * CD + c);
    *(float4*)(out + (size_t)p * CD + c) = make_float4(v.x * ic, v.y * ic, v.z * ic, v.w * ic);
}

// ---------------- launch ----------------
extern "C" void kernel_launch(void* const* d_in, const int* in_sizes, int n_in,
                              void* d_out, int out_size) {
    const float* feat = (const float*)d_in[0];
    const float* vfea = (const float*)d_in[1];
    const int*   inv  = (const int*)d_in[2];
    const int*   cil  = (const int*)d_in[3];
    const int*   cin  = (const int*)d_in[4];
    const float* W_in = (const float*)d_in[5];
    const float* b_in = (const float*)d_in[6];
    const float* W1   = (const float*)d_in[7];
    const float* b1   = (const float*)d_in[8];
    const float* g1   = (const float*)d_in[9];
    const float* be1  = (const float*)d_in[10];
    const float* W2   = (const float*)d_in[11];
    const float* b2   = (const float*)d_in[12];
    const float* g2   = (const float*)d_in[13];
    const float* be2  = (const float*)d_in[14];
    const float* W3   = (const float*)d_in[15];
    const float* b3   = (const float*)d_in[16];
    const float* Wo1  = (const float*)d_in[17];
    const float* bo1  = (const float*)d_in[18];
    const float* Wo2  = (const float*)d_in[19];
    const float* bo2  = (const float*)d_in[20];
    float* out = (float*)d_out;

    const int PTS_SMEM = 60928;
    const int ID_SMEM  = 69632;
    cudaFuncSetAttribute(k_points, cudaFuncAttributeMaxDynamicSharedMemorySize, PTS_SMEM);
    cudaFuncSetAttribute(k_identity, cudaFuncAttributeMaxDynamicSharedMemorySize, ID_SMEM);

    k_zero<<<2048, 256>>>();
    k_prep<<<128, 256>>>(Wo1, Wo2, W_in);
    k_counts<<<(NPTS + 255) / 256, 256>>>(inv, cin);
    k_identity<<<(NV + 127) / 128, 256, ID_SMEM>>>(feat, vfea, inv, b_in);
    k_mlp1<<<(ND + 127) / 128, 256>>>(W1, b1);
    k_mlp2<<<(ND + 127) / 128, 256>>>(g1, be1, W2, b2);
    k_mlp3<<<(ND + 127) / 128, 256>>>(g2, be2, W3, b3);
    k_points<<<NPTS / 128, 256, PTS_SMEM>>>(cil, cin, inv, bo1, bo2);
    k_gather<<<(NPTS * 32) / 256, 256>>>(cin, out);
}